// round 1
// baseline (speedup 1.0000x reference)
#include <cuda_runtime.h>
#include <math.h>

#define NN 8192
#define HID 64
#define MAXC 160

// ---------------- device scratch (no allocs allowed) ----------------
__device__ float g_z1[NN * HID];      // normalized projection of x1
__device__ float g_z2[NN * HID];      // normalized projection of x2
__device__ float g_rowsum[NN];        // sum_j S[i,j]
__device__ float g_colsum[NN];        // sum_i S[i,j]
__device__ int   g_cnt[NN];           // nnz per row of positive_matrix
__device__ int   g_cols[NN * MAXC];   // column indices of positives

// e^x for |x| <= ~1.3 : degree-8 Taylor, 9 FMAs, rel err ~4e-5
__device__ __forceinline__ float exp_poly(float x) {
    float p = 2.4801587e-5f;          // 1/40320
    p = fmaf(p, x, 1.9841270e-4f);    // 1/5040
    p = fmaf(p, x, 1.3888889e-3f);    // 1/720
    p = fmaf(p, x, 8.3333333e-3f);    // 1/120
    p = fmaf(p, x, 4.1666667e-2f);    // 1/24
    p = fmaf(p, x, 1.6666667e-1f);    // 1/6
    p = fmaf(p, x, 0.5f);
    p = fmaf(p, x, 1.0f);
    p = fmaf(p, x, 1.0f);
    return p;
}

// ---------------- K1: projection + ELU + projection + L2 norm ----------------
// z = (ELU(x @ W1^T + b1)) @ W2^T + b2 ; zhat = z / max(||z||, 1e-12)
// 8 rows per block (warp per row). 2048 blocks cover x1 then x2.
__global__ void __launch_bounds__(256) proj_kernel(
    const float* __restrict__ x1, const float* __restrict__ x2,
    const float* __restrict__ W1, const float* __restrict__ b1,
    const float* __restrict__ W2, const float* __restrict__ b2)
{
    __shared__ float sW1[64 * 65];
    __shared__ float sW2[64 * 65];
    __shared__ float sX[8][64];
    __shared__ float sH[8][64];

    int tid = threadIdx.x;
    for (int idx = tid; idx < 4096; idx += 256) {
        int r = idx >> 6, c = idx & 63;
        sW1[r * 65 + c] = W1[idx];
        sW2[r * 65 + c] = W2[idx];
    }
    __syncthreads();

    int w = tid >> 5, lane = tid & 31;
    int row = blockIdx.x * 8 + w;
    const float* x; float* out; int r;
    if (row < NN) { x = x1; out = g_z1; r = row; }
    else          { x = x2; out = g_z2; r = row - NN; }

    sX[w][lane]      = x[r * 64 + lane];
    sX[w][lane + 32] = x[r * 64 + lane + 32];
    __syncwarp();

    int c0 = lane, c1 = lane + 32;
    float a0 = b1[c0], a1 = b1[c1];
#pragma unroll
    for (int k = 0; k < 64; k++) {
        float xv = sX[w][k];
        a0 = fmaf(xv, sW1[c0 * 65 + k], a0);
        a1 = fmaf(xv, sW1[c1 * 65 + k], a1);
    }
    a0 = (a0 > 0.0f) ? a0 : expm1f(a0);   // ELU alpha=1
    a1 = (a1 > 0.0f) ? a1 : expm1f(a1);
    sH[w][c0] = a0; sH[w][c1] = a1;
    __syncwarp();

    float z0 = b2[c0], z1v = b2[c1];
#pragma unroll
    for (int k = 0; k < 64; k++) {
        float hv = sH[w][k];
        z0  = fmaf(hv, sW2[c0 * 65 + k], z0);
        z1v = fmaf(hv, sW2[c1 * 65 + k], z1v);
    }
    float ss = z0 * z0 + z1v * z1v;
#pragma unroll
    for (int o = 16; o > 0; o >>= 1) ss += __shfl_xor_sync(0xffffffffu, ss, o);
    float inv = 1.0f / fmaxf(sqrtf(ss), 1e-12f);
    out[r * 64 + c0] = z0 * inv;
    out[r * 64 + c1] = z1v * inv;
}

// ---------------- K_scan: dense 256MB positive_matrix -> per-row index lists ----------------
__global__ void __launch_bounds__(256) scan_kernel(const float* __restrict__ pos)
{
    const float4* p4 = reinterpret_cast<const float4*>(pos);
    int total = NN * (NN / 4);   // 16,777,216 float4s
    int stride = gridDim.x * blockDim.x;
    for (int idx = blockIdx.x * blockDim.x + threadIdx.x; idx < total; idx += stride) {
        float4 v = p4[idx];
        if (v.x != 0.0f || v.y != 0.0f || v.z != 0.0f || v.w != 0.0f) {
            int base = idx << 2;
            int row = base >> 13;
            int col = base & (NN - 1);
            if (v.x != 0.0f) { int p = atomicAdd(&g_cnt[row], 1); if (p < MAXC) g_cols[row * MAXC + p] = col; }
            if (v.y != 0.0f) { int p = atomicAdd(&g_cnt[row], 1); if (p < MAXC) g_cols[row * MAXC + p] = col + 1; }
            if (v.z != 0.0f) { int p = atomicAdd(&g_cnt[row], 1); if (p < MAXC) g_cols[row * MAXC + p] = col + 2; }
            if (v.w != 0.0f) { int p = atomicAdd(&g_cnt[row], 1); if (p < MAXC) g_cols[row * MAXC + p] = col + 3; }
        }
    }
}

// ---------------- K2: rowsum/colsum of exp(z1hat @ z2hat^T / tau) ----------------
// 128x128 tile per block, 8x8 register micro-tile, k-major smem (pad 132) for
// conflict-free float4 fragment loads. Smem reused for the row/col reduction.
__global__ void __launch_bounds__(256, 2) sim_kernel()
{
    extern __shared__ float sm[];
    float* sA = sm;               // [64][132]
    float* sB = sm + 64 * 132;    // [64][132]

    int tid = threadIdx.x;
    int bi = blockIdx.y, bj = blockIdx.x;
    const float* Za = g_z1 + bi * 128 * 64;
    const float* Zb = g_z2 + bj * 128 * 64;

    for (int idx = tid; idx < 128 * 64; idx += 256) {
        int i = idx >> 6, k = idx & 63;
        sA[k * 132 + i] = Za[idx];
        sB[k * 132 + i] = Zb[idx];
    }
    __syncthreads();

    int ti = tid >> 4, tj = tid & 15;
    float acc[8][8];
#pragma unroll
    for (int ii = 0; ii < 8; ii++)
#pragma unroll
        for (int jj = 0; jj < 8; jj++) acc[ii][jj] = 0.0f;

    const float* pA = sA + ti * 8;
    const float* pB = sB + tj * 8;
#pragma unroll 8
    for (int k = 0; k < 64; k++) {
        float4 a0 = *reinterpret_cast<const float4*>(pA + k * 132);
        float4 a1 = *reinterpret_cast<const float4*>(pA + k * 132 + 4);
        float4 b0 = *reinterpret_cast<const float4*>(pB + k * 132);
        float4 b1 = *reinterpret_cast<const float4*>(pB + k * 132 + 4);
        float av[8] = {a0.x, a0.y, a0.z, a0.w, a1.x, a1.y, a1.z, a1.w};
        float bv[8] = {b0.x, b0.y, b0.z, b0.w, b1.x, b1.y, b1.z, b1.w};
#pragma unroll
        for (int ii = 0; ii < 8; ii++)
#pragma unroll
            for (int jj = 0; jj < 8; jj++)
                acc[ii][jj] = fmaf(av[ii], bv[jj], acc[ii][jj]);
    }

    float rs[8] = {0, 0, 0, 0, 0, 0, 0, 0};
    float cs[8] = {0, 0, 0, 0, 0, 0, 0, 0};
#pragma unroll
    for (int ii = 0; ii < 8; ii++)
#pragma unroll
        for (int jj = 0; jj < 8; jj++) {
            float e = exp_poly(acc[ii][jj] * 1.25f);   // 1/TAU
            rs[ii] += e;
            cs[jj] += e;
        }

    __syncthreads();   // everyone done reading tiles; reuse smem for staging
    float* rowp = sm;              // [16][132]
    float* colp = sm + 16 * 132;   // [16][132]
#pragma unroll
    for (int ii = 0; ii < 8; ii++) rowp[tj * 132 + ti * 8 + ii] = rs[ii];
#pragma unroll
    for (int jj = 0; jj < 8; jj++) colp[ti * 132 + tj * 8 + jj] = cs[jj];
    __syncthreads();

    if (tid < 128) {
        float s = 0.0f, c = 0.0f;
#pragma unroll
        for (int t = 0; t < 16; t++) {
            s += rowp[t * 132 + tid];
            c += colp[t * 132 + tid];
        }
        atomicAdd(&g_rowsum[bi * 128 + tid], s);
        atomicAdd(&g_colsum[bj * 128 + tid], c);
    }
}

// ---------------- K3: sparse numerators + final loss ----------------
// warp per row i: num_sc[i] = sum_{j in pos(i)} exp(a_i.b_j/tau)
//                 num_mp[i] = sum_{j in pos(i)} exp(a_j.b_i/tau)
__global__ void __launch_bounds__(256) loss_kernel(float* __restrict__ out)
{
    __shared__ float sA[8][64];
    __shared__ float sB[8][64];
    __shared__ float wsum[8];

    int tid = threadIdx.x, w = tid >> 5, lane = tid & 31;
    int i = blockIdx.x * 8 + w;

    sA[w][lane]      = g_z1[i * 64 + lane];
    sA[w][lane + 32] = g_z1[i * 64 + lane + 32];
    sB[w][lane]      = g_z2[i * 64 + lane];
    sB[w][lane + 32] = g_z2[i * 64 + lane + 32];
    __syncwarp();

    int cnt = min(g_cnt[i], MAXC);
    float ns = 0.0f, ms = 0.0f;
    const float4* a4 = reinterpret_cast<const float4*>(&sA[w][0]);
    const float4* b4 = reinterpret_cast<const float4*>(&sB[w][0]);

    for (int b = 0; b < cnt; b += 32) {
        int idx = b + lane;
        if (idx < cnt) {
            int j = g_cols[i * MAXC + idx];
            const float4* z2j = reinterpret_cast<const float4*>(g_z2 + j * 64);
            const float4* z1j = reinterpret_cast<const float4*>(g_z1 + j * 64);
            float d1 = 0.0f, d2 = 0.0f;
#pragma unroll
            for (int q = 0; q < 16; q++) {
                float4 u = z2j[q], a = a4[q];
                d1 = fmaf(u.x, a.x, d1); d1 = fmaf(u.y, a.y, d1);
                d1 = fmaf(u.z, a.z, d1); d1 = fmaf(u.w, a.w, d1);
                float4 t = z1j[q], bb = b4[q];
                d2 = fmaf(t.x, bb.x, d2); d2 = fmaf(t.y, bb.y, d2);
                d2 = fmaf(t.z, bb.z, d2); d2 = fmaf(t.w, bb.w, d2);
            }
            ns += exp_poly(d1 * 1.25f);
            ms += exp_poly(d2 * 1.25f);
        }
    }
#pragma unroll
    for (int o = 16; o > 0; o >>= 1) {
        ns += __shfl_xor_sync(0xffffffffu, ns, o);
        ms += __shfl_xor_sync(0xffffffffu, ms, o);
    }
    if (lane == 0) {
        float rsum = g_rowsum[i] + 1e-8f;
        float csum = g_colsum[i] + 1e-8f;
        // loss = 0.5*mean(-log(ns/rsum+1e-8)) + 0.5*mean(-log(ms/csum+1e-8))
        float term = -0.5f * (logf(ns / rsum + 1e-8f) + logf(ms / csum + 1e-8f)) * (1.0f / NN);
        wsum[w] = term;
    }
    __syncthreads();
    if (tid == 0) {
        float s = 0.0f;
#pragma unroll
        for (int t = 0; t < 8; t++) s += wsum[t];
        atomicAdd(out, s);
    }
}

// ---------------- host launcher ----------------
extern "C" void kernel_launch(void* const* d_in, const int* in_sizes, int n_in,
                              void* d_out, int out_size)
{
    const float* x1  = (const float*)d_in[0];
    const float* x2  = (const float*)d_in[1];
    const float* W1  = (const float*)d_in[2];
    const float* b1  = (const float*)d_in[3];
    const float* W2  = (const float*)d_in[4];
    const float* b2  = (const float*)d_in[5];
    const float* pos = (const float*)d_in[6];

    void *prow, *pcol, *pcnt;
    cudaGetSymbolAddress(&prow, g_rowsum);
    cudaGetSymbolAddress(&pcol, g_colsum);
    cudaGetSymbolAddress(&pcnt, g_cnt);
    cudaMemsetAsync(prow, 0, NN * sizeof(float), 0);
    cudaMemsetAsync(pcol, 0, NN * sizeof(float), 0);
    cudaMemsetAsync(pcnt, 0, NN * sizeof(int), 0);
    cudaMemsetAsync(d_out, 0, sizeof(float), 0);

    proj_kernel<<<2048, 256>>>(x1, x2, W1, b1, W2, b2);
    scan_kernel<<<4096, 256>>>(pos);

    cudaFuncSetAttribute(sim_kernel, cudaFuncAttributeMaxDynamicSharedMemorySize, 67584);
    sim_kernel<<<dim3(64, 64), 256, 67584>>>();

    loss_kernel<<<1024, 256>>>((float*)d_out);
}

// round 2
// speedup vs baseline: 1.1781x; 1.1781x over previous
#include <cuda_runtime.h>
#include <math.h>

#define NN 8192
#define HID 64

// ---------------- device scratch (no allocs allowed) ----------------
__device__ float g_z1[NN * HID];      // normalized projection of x1
__device__ float g_z2[NN * HID];      // normalized projection of x2
__device__ float g_rowsum[NN];        // sum_j S[i,j]
__device__ float g_colsum[NN];        // sum_i S[i,j]
__device__ float g_num1[NN];          // sum_j pos[i,j] * S[i,j]
__device__ float g_num2[NN];          // sum_j pos[i,j] * S[j,i]

// ---------------- packed f32x2 helpers (FFMA2 path, sm_100+) ----------------
__device__ __forceinline__ float2 ffma2(float2 a, float2 b, float2 c) {
    float2 d;
    asm("fma.rn.f32x2 %0, %1, %2, %3;"
        : "=l"(reinterpret_cast<unsigned long long&>(d))
        : "l"(reinterpret_cast<unsigned long long&>(a)),
          "l"(reinterpret_cast<unsigned long long&>(b)),
          "l"(reinterpret_cast<unsigned long long&>(c)));
    return d;
}
__device__ __forceinline__ float2 fadd2(float2 a, float2 b) {
    float2 d;
    asm("add.rn.f32x2 %0, %1, %2;"
        : "=l"(reinterpret_cast<unsigned long long&>(d))
        : "l"(reinterpret_cast<unsigned long long&>(a)),
          "l"(reinterpret_cast<unsigned long long&>(b)));
    return d;
}
__device__ __forceinline__ float2 fmul2(float2 a, float2 b) {
    float2 d;
    asm("mul.rn.f32x2 %0, %1, %2;"
        : "=l"(reinterpret_cast<unsigned long long&>(d))
        : "l"(reinterpret_cast<unsigned long long&>(a)),
          "l"(reinterpret_cast<unsigned long long&>(b)));
    return d;
}
__device__ __forceinline__ float2 dup2(float c) { return make_float2(c, c); }

// e^y for |y| <= ~1.3 : degree-8 Taylor on packed pairs (y already scaled by 1/tau)
__device__ __forceinline__ float2 exp_poly2(float2 y) {
    float2 p = dup2(2.4801587e-5f);          // 1/40320
    p = ffma2(p, y, dup2(1.9841270e-4f));    // 1/5040
    p = ffma2(p, y, dup2(1.3888889e-3f));    // 1/720
    p = ffma2(p, y, dup2(8.3333333e-3f));    // 1/120
    p = ffma2(p, y, dup2(4.1666667e-2f));    // 1/24
    p = ffma2(p, y, dup2(1.6666667e-1f));    // 1/6
    p = ffma2(p, y, dup2(0.5f));
    p = ffma2(p, y, dup2(1.0f));
    p = ffma2(p, y, dup2(1.0f));
    return p;
}

// ---------------- K1: projection + ELU + projection + L2 norm ----------------
__global__ void __launch_bounds__(256) proj_kernel(
    const float* __restrict__ x1, const float* __restrict__ x2,
    const float* __restrict__ W1, const float* __restrict__ b1,
    const float* __restrict__ W2, const float* __restrict__ b2)
{
    __shared__ float sW1[64 * 65];
    __shared__ float sW2[64 * 65];
    __shared__ float sX[8][64];
    __shared__ float sH[8][64];

    int tid = threadIdx.x;
    for (int idx = tid; idx < 4096; idx += 256) {
        int r = idx >> 6, c = idx & 63;
        sW1[r * 65 + c] = W1[idx];
        sW2[r * 65 + c] = W2[idx];
    }
    __syncthreads();

    int w = tid >> 5, lane = tid & 31;
    int row = blockIdx.x * 8 + w;
    const float* x; float* out; int r;
    if (row < NN) { x = x1; out = g_z1; r = row; }
    else          { x = x2; out = g_z2; r = row - NN; }

    sX[w][lane]      = x[r * 64 + lane];
    sX[w][lane + 32] = x[r * 64 + lane + 32];
    __syncwarp();

    int c0 = lane, c1 = lane + 32;
    float a0 = b1[c0], a1 = b1[c1];
#pragma unroll
    for (int k = 0; k < 64; k++) {
        float xv = sX[w][k];
        a0 = fmaf(xv, sW1[c0 * 65 + k], a0);
        a1 = fmaf(xv, sW1[c1 * 65 + k], a1);
    }
    a0 = (a0 > 0.0f) ? a0 : expm1f(a0);   // ELU alpha=1
    a1 = (a1 > 0.0f) ? a1 : expm1f(a1);
    sH[w][c0] = a0; sH[w][c1] = a1;
    __syncwarp();

    float z0 = b2[c0], z1v = b2[c1];
#pragma unroll
    for (int k = 0; k < 64; k++) {
        float hv = sH[w][k];
        z0  = fmaf(hv, sW2[c0 * 65 + k], z0);
        z1v = fmaf(hv, sW2[c1 * 65 + k], z1v);
    }
    float ss = z0 * z0 + z1v * z1v;
#pragma unroll
    for (int o = 16; o > 0; o >>= 1) ss += __shfl_xor_sync(0xffffffffu, ss, o);
    float inv = 1.0f / fmaxf(sqrtf(ss), 1e-12f);
    out[r * 64 + c0] = z0 * inv;
    out[r * 64 + c1] = z1v * inv;
}

// ---------------- K2: fused similarity + row/col sums + masked numerators ----
// 128x128 tile per block; 8x8 micro-tile packed as 8x4 f32x2 accumulators.
// Epilogue reads the positive-mask tile (and its transpose sibling) directly
// from global; since mask values are exactly 0.0/1.0, the numerators are FMAs.
__global__ void __launch_bounds__(256, 2) sim_fused_kernel(const float* __restrict__ pos)
{
    extern __shared__ float sm[];
    float* sA = sm;               // [64][132] k-major
    float* sB = sm + 64 * 132;    // [64][132]

    int tid = threadIdx.x;
    int bi = blockIdx.y, bj = blockIdx.x;
    const float* Za = g_z1 + bi * 128 * 64;
    const float* Zb = g_z2 + bj * 128 * 64;

    for (int idx = tid; idx < 128 * 64; idx += 256) {
        int i = idx >> 6, k = idx & 63;
        sA[k * 132 + i] = Za[idx];
        sB[k * 132 + i] = Zb[idx];
    }
    __syncthreads();

    int ti = tid >> 4, tj = tid & 15;
    float2 acc[8][4];
#pragma unroll
    for (int ii = 0; ii < 8; ii++)
#pragma unroll
        for (int jp = 0; jp < 4; jp++) acc[ii][jp] = make_float2(0.0f, 0.0f);

    const float* pA = sA + ti * 8;
    const float* pB = sB + tj * 8;
#pragma unroll 8
    for (int k = 0; k < 64; k++) {
        float4 A0 = *reinterpret_cast<const float4*>(pA + k * 132);
        float4 A1 = *reinterpret_cast<const float4*>(pA + k * 132 + 4);
        float4 B0 = *reinterpret_cast<const float4*>(pB + k * 132);
        float4 B1 = *reinterpret_cast<const float4*>(pB + k * 132 + 4);
        float av[8] = {A0.x, A0.y, A0.z, A0.w, A1.x, A1.y, A1.z, A1.w};
        float2 bv[4] = {{B0.x, B0.y}, {B0.z, B0.w}, {B1.x, B1.y}, {B1.z, B1.w}};
#pragma unroll
        for (int ii = 0; ii < 8; ii++) {
            float2 ad = make_float2(av[ii], av[ii]);
#pragma unroll
            for (int jp = 0; jp < 4; jp++)
                acc[ii][jp] = ffma2(ad, bv[jp], acc[ii][jp]);
        }
    }

    // -------- epilogue pass A: exp, row sums, col sums, num_sc (mask tile M1) --------
    const float2 tauinv = dup2(1.25f);   // 1/TAU
    float rs[8], nr[8];
    float2 csp[4];
#pragma unroll
    for (int jp = 0; jp < 4; jp++) csp[jp] = make_float2(0.0f, 0.0f);

    int r0 = bi * 128 + ti * 8;
    int c0 = bj * 128 + tj * 8;

#pragma unroll
    for (int ii = 0; ii < 8; ii++) {
        const float* m1row = pos + (size_t)(r0 + ii) * NN + c0;
        float4 M0 = *reinterpret_cast<const float4*>(m1row);
        float4 M1v = *reinterpret_cast<const float4*>(m1row + 4);
        float2 m1p[4] = {{M0.x, M0.y}, {M0.z, M0.w}, {M1v.x, M1v.y}, {M1v.z, M1v.w}};

        float2 e0 = exp_poly2(fmul2(acc[ii][0], tauinv));
        float2 e1 = exp_poly2(fmul2(acc[ii][1], tauinv));
        float2 e2 = exp_poly2(fmul2(acc[ii][2], tauinv));
        float2 e3 = exp_poly2(fmul2(acc[ii][3], tauinv));
        acc[ii][0] = e0; acc[ii][1] = e1; acc[ii][2] = e2; acc[ii][3] = e3;

        float2 t = fadd2(fadd2(e0, e1), fadd2(e2, e3));
        rs[ii] = t.x + t.y;

        csp[0] = fadd2(csp[0], e0);
        csp[1] = fadd2(csp[1], e1);
        csp[2] = fadd2(csp[2], e2);
        csp[3] = fadd2(csp[3], e3);

        float2 q = ffma2(e0, m1p[0],
                   ffma2(e1, m1p[1],
                   ffma2(e2, m1p[2], fmul2(e3, m1p[3]))));
        nr[ii] = q.x + q.y;
    }

    // -------- epilogue pass B: num_mp needs pos[c, r] (transpose sibling tile) --------
    float nc[8];
#pragma unroll
    for (int jj = 0; jj < 8; jj++) {
        const float* m2row = pos + (size_t)(c0 + jj) * NN + r0;
        float4 M0 = *reinterpret_cast<const float4*>(m2row);
        float4 M1v = *reinterpret_cast<const float4*>(m2row + 4);
        float m2v[8] = {M0.x, M0.y, M0.z, M0.w, M1v.x, M1v.y, M1v.z, M1v.w};
        float ncv = 0.0f;
#pragma unroll
        for (int ii = 0; ii < 8; ii++) {
            float ev = (jj & 1) ? acc[ii][jj >> 1].y : acc[ii][jj >> 1].x;
            ncv = fmaf(ev, m2v[ii], ncv);
        }
        nc[jj] = ncv;
    }

    // -------- stage partials through smem, one atomic per row/col per block --------
    __syncthreads();   // everyone done reading sA/sB
    float* rowp  = sm;              // [16][132]
    float* nrowp = sm + 2112;
    float* colp  = sm + 4224;
    float* ncolp = sm + 6336;
#pragma unroll
    for (int ii = 0; ii < 8; ii++) {
        rowp [tj * 132 + ti * 8 + ii] = rs[ii];
        nrowp[tj * 132 + ti * 8 + ii] = nr[ii];
    }
#pragma unroll
    for (int jj = 0; jj < 8; jj++) {
        float cv = (jj & 1) ? csp[jj >> 1].y : csp[jj >> 1].x;
        colp [ti * 132 + tj * 8 + jj] = cv;
        ncolp[ti * 132 + tj * 8 + jj] = nc[jj];
    }
    __syncthreads();

    if (tid < 128) {
        float s = 0.0f, n1 = 0.0f, c = 0.0f, n2 = 0.0f;
#pragma unroll
        for (int t = 0; t < 16; t++) {
            s  += rowp [t * 132 + tid];
            n1 += nrowp[t * 132 + tid];
            c  += colp [t * 132 + tid];
            n2 += ncolp[t * 132 + tid];
        }
        atomicAdd(&g_rowsum[bi * 128 + tid], s);
        atomicAdd(&g_num1  [bi * 128 + tid], n1);
        atomicAdd(&g_colsum[bj * 128 + tid], c);
        atomicAdd(&g_num2  [bj * 128 + tid], n2);
    }
}

// ---------------- K3: final loss reduction ----------------
__global__ void __launch_bounds__(256) final_kernel(float* __restrict__ out)
{
    __shared__ float red[8];
    int i = blockIdx.x * 256 + threadIdx.x;
    float rsum = g_rowsum[i] + 1e-8f;
    float csum = g_colsum[i] + 1e-8f;
    float term = -0.5f * (logf(g_num1[i] / rsum + 1e-8f) +
                          logf(g_num2[i] / csum + 1e-8f)) * (1.0f / NN);
#pragma unroll
    for (int o = 16; o > 0; o >>= 1) term += __shfl_xor_sync(0xffffffffu, term, o);
    int w = threadIdx.x >> 5, lane = threadIdx.x & 31;
    if (lane == 0) red[w] = term;
    __syncthreads();
    if (threadIdx.x == 0) {
        float s = 0.0f;
#pragma unroll
        for (int t = 0; t < 8; t++) s += red[t];
        atomicAdd(out, s);
    }
}

// ---------------- host launcher ----------------
extern "C" void kernel_launch(void* const* d_in, const int* in_sizes, int n_in,
                              void* d_out, int out_size)
{
    const float* x1  = (const float*)d_in[0];
    const float* x2  = (const float*)d_in[1];
    const float* W1  = (const float*)d_in[2];
    const float* b1  = (const float*)d_in[3];
    const float* W2  = (const float*)d_in[4];
    const float* b2  = (const float*)d_in[5];
    const float* pos = (const float*)d_in[6];

    void *p;
    cudaGetSymbolAddress(&p, g_rowsum); cudaMemsetAsync(p, 0, NN * sizeof(float), 0);
    cudaGetSymbolAddress(&p, g_colsum); cudaMemsetAsync(p, 0, NN * sizeof(float), 0);
    cudaGetSymbolAddress(&p, g_num1);   cudaMemsetAsync(p, 0, NN * sizeof(float), 0);
    cudaGetSymbolAddress(&p, g_num2);   cudaMemsetAsync(p, 0, NN * sizeof(float), 0);
    cudaMemsetAsync(d_out, 0, sizeof(float), 0);

    proj_kernel<<<2048, 256>>>(x1, x2, W1, b1, W2, b2);

    cudaFuncSetAttribute(sim_fused_kernel, cudaFuncAttributeMaxDynamicSharedMemorySize, 67584);
    sim_fused_kernel<<<dim3(64, 64), 256, 67584>>>(pos);

    final_kernel<<<32, 256>>>((float*)d_out);
}

// round 5
// speedup vs baseline: 2.0755x; 1.7617x over previous
#include <cuda_runtime.h>
#include <cuda_bf16.h>
#include <cstdint>
#include <math.h>

#define NN 8192
#define HID 64

// ---------------- device scratch (no allocs allowed) ----------------
__device__ __align__(16) __nv_bfloat16 g_z1h[NN * HID];   // normalized proj of x1 (bf16)
__device__ __align__(16) __nv_bfloat16 g_z2h[NN * HID];   // normalized proj of x2 (bf16)
__device__ float g_rowsum[NN];
__device__ float g_colsum[NN];
__device__ float g_num1[NN];
__device__ float g_num2[NN];

// ---------------- PTX helpers (baseline features only: sm_80-class) ----------------
__device__ __forceinline__ uint32_t smem_u32(const void* p) {
    uint32_t a;
    asm("{ .reg .u64 t; cvta.to.shared.u64 t, %1; cvt.u32.u64 %0, t; }" : "=r"(a) : "l"(p));
    return a;
}
__device__ __forceinline__ float ex2f(float x) {
    float y; asm("ex2.approx.ftz.f32 %0, %1;" : "=f"(y) : "f"(x)); return y;
}
#define SWZ128(o) ((o) ^ (((o) >> 3) & 0x70))

__device__ __forceinline__ void ldsm_x4(uint32_t* r, uint32_t addr) {
    asm volatile("ldmatrix.sync.aligned.m8n8.x4.shared.b16 {%0,%1,%2,%3}, [%4];"
                 : "=r"(r[0]), "=r"(r[1]), "=r"(r[2]), "=r"(r[3]) : "r"(addr));
}
// D += A(16x16 bf16, row) * B(16x8 bf16, col)   [f32 accum]
__device__ __forceinline__ void mma16816(float* d, const uint32_t* a, const uint32_t* b) {
    asm volatile(
        "mma.sync.aligned.m16n8k16.row.col.f32.bf16.bf16.f32 "
        "{%0,%1,%2,%3}, {%4,%5,%6,%7}, {%8,%9}, {%0,%1,%2,%3};"
        : "+f"(d[0]), "+f"(d[1]), "+f"(d[2]), "+f"(d[3])
        : "r"(a[0]), "r"(a[1]), "r"(a[2]), "r"(a[3]), "r"(b[0]), "r"(b[1]));
}

// ---------------- K1: projection + ELU + projection + L2 norm -> bf16 ----------------
__global__ void __launch_bounds__(256) proj_kernel(
    const float* __restrict__ x1, const float* __restrict__ x2,
    const float* __restrict__ W1, const float* __restrict__ b1,
    const float* __restrict__ W2, const float* __restrict__ b2)
{
    __shared__ float sW1[64 * 68];
    __shared__ float sW2[64 * 68];
    __shared__ float sX[8][64];
    __shared__ float sH[8][64];

    int tid = threadIdx.x;
    for (int idx = tid; idx < 4096; idx += 256) {
        int r = idx >> 6, c = idx & 63;
        sW1[r * 68 + c] = W1[idx];
        sW2[r * 68 + c] = W2[idx];
    }
    __syncthreads();

    int w = tid >> 5, lane = tid & 31;
    int row = blockIdx.x * 8 + w;
    const float* x; __nv_bfloat16* out; int r;
    if (row < NN) { x = x1; out = g_z1h; r = row; }
    else          { x = x2; out = g_z2h; r = row - NN; }

    sX[w][lane]      = x[r * 64 + lane];
    sX[w][lane + 32] = x[r * 64 + lane + 32];
    __syncwarp();

    int c0 = lane, c1 = lane + 32;
    const float4* x4  = reinterpret_cast<const float4*>(&sX[w][0]);
    const float4* w1a = reinterpret_cast<const float4*>(sW1 + c0 * 68);
    const float4* w1b = reinterpret_cast<const float4*>(sW1 + c1 * 68);
    float a0 = b1[c0], a1 = b1[c1];
#pragma unroll
    for (int kq = 0; kq < 16; kq++) {
        float4 xq = x4[kq], u = w1a[kq], v = w1b[kq];
        a0 = fmaf(xq.x, u.x, a0); a0 = fmaf(xq.y, u.y, a0);
        a0 = fmaf(xq.z, u.z, a0); a0 = fmaf(xq.w, u.w, a0);
        a1 = fmaf(xq.x, v.x, a1); a1 = fmaf(xq.y, v.y, a1);
        a1 = fmaf(xq.z, v.z, a1); a1 = fmaf(xq.w, v.w, a1);
    }
    a0 = (a0 > 0.0f) ? a0 : expm1f(a0);   // ELU alpha=1
    a1 = (a1 > 0.0f) ? a1 : expm1f(a1);
    sH[w][c0] = a0; sH[w][c1] = a1;
    __syncwarp();

    const float4* h4  = reinterpret_cast<const float4*>(&sH[w][0]);
    const float4* w2a = reinterpret_cast<const float4*>(sW2 + c0 * 68);
    const float4* w2b = reinterpret_cast<const float4*>(sW2 + c1 * 68);
    float z0 = b2[c0], z1v = b2[c1];
#pragma unroll
    for (int kq = 0; kq < 16; kq++) {
        float4 hq = h4[kq], u = w2a[kq], v = w2b[kq];
        z0  = fmaf(hq.x, u.x, z0);  z0  = fmaf(hq.y, u.y, z0);
        z0  = fmaf(hq.z, u.z, z0);  z0  = fmaf(hq.w, u.w, z0);
        z1v = fmaf(hq.x, v.x, z1v); z1v = fmaf(hq.y, v.y, z1v);
        z1v = fmaf(hq.z, v.z, z1v); z1v = fmaf(hq.w, v.w, z1v);
    }
    float ss = z0 * z0 + z1v * z1v;
#pragma unroll
    for (int o = 16; o > 0; o >>= 1) ss += __shfl_xor_sync(0xffffffffu, ss, o);
    float inv = 1.0f / fmaxf(sqrtf(ss), 1e-12f);
    out[r * 64 + c0] = __float2bfloat16(z0 * inv);
    out[r * 64 + c1] = __float2bfloat16(z1v * inv);
}

// ---------------- K2: warp-MMA similarity, fully row-aligned reductions ----------------
// Block (bi,bj):  T1 = z1[bi] @ z2[bj]^T -> rowsum/num1 (rows of S)
//                 T2 = z2[bi] @ z1[bj]^T -> colsum/num2 (rows of S^T)
// Both consume the SAME pos tile pos[bi-rows, bj-cols], read exactly once.
#define SMEM_A1 0
#define SMEM_B1 16384
#define SMEM_A2 32768
#define SMEM_B2 49152
#define SMEM_TOT 65536

__global__ void __launch_bounds__(256, 2) sim_mma_kernel(const float* __restrict__ pos)
{
    extern __shared__ char smem[];
    uint32_t sbase = smem_u32(smem);
    int tid = threadIdx.x, w = tid >> 5, lane = tid & 31;
    int bi = blockIdx.y, bj = blockIdx.x;

    // ---- load 4 bf16 tiles (SW128-swizzled): A1=z1[bi], B1=z2[bj], A2=z2[bi], B2=z1[bj]
    {
        const float4* z1f = reinterpret_cast<const float4*>(g_z1h);
        const float4* z2f = reinterpret_cast<const float4*>(g_z2h);
        const float4* gsrc[4] = { z1f + bi * 1024, z2f + bj * 1024,
                                  z2f + bi * 1024, z1f + bj * 1024 };
#pragma unroll
        for (int t = 0; t < 4; t++) {
            char* dst = smem + t * 16384;
            for (int idx = tid; idx < 1024; idx += 256) {
                int rrow = idx >> 3, q = idx & 7;
                uint32_t sw = SWZ128((uint32_t)(rrow * 128 + q * 16));
                *reinterpret_cast<float4*>(dst + sw) = gsrc[t][idx];
            }
        }
    }
    __syncthreads();

    // ---- A fragments (rows 16w..16w+15, K=64) for both tiles, loaded once
    int rr = lane & 7, g = lane >> 3;
    uint32_t a1[16], a2[16];
    {
        int rowA = 16 * w + (g & 1) * 8 + rr;   // groups 0,1 -> rows 0-7 / 8-15
        int chA  = (g >> 1);                    // groups 0,1 chunk +0 ; 2,3 chunk +1
#pragma unroll
        for (int s = 0; s < 4; s++) {
            uint32_t off = SWZ128((uint32_t)(rowA * 128 + (2 * s + chA) * 16));
            ldsm_x4(a1 + 4 * s, sbase + SMEM_A1 + off);
            ldsm_x4(a2 + 4 * s, sbase + SMEM_A2 + off);
        }
    }

    // ---- sweep 16 n-fragments of 8 cols
    int qr = lane >> 2, qc = lane & 3;
    int R0 = bi * 128 + 16 * w + qr;            // global rows owned by this thread
    const float* pr0 = pos + (size_t)R0 * NN + bj * 128 + 2 * qc;
    const float* pr1 = pr0 + (size_t)8 * NN;

    float rs1a = 0.f, rs1b = 0.f, nm1a = 0.f, nm1b = 0.f;
    float rs2a = 0.f, rs2b = 0.f, nm2a = 0.f, nm2b = 0.f;
    const float cexp = 1.8033688011f;           // log2(e)/tau

#pragma unroll
    for (int nf = 0; nf < 16; nf++) {
        // pos for this fragment (shared by T1 and T2)
        float2 p0 = *reinterpret_cast<const float2*>(pr0 + nf * 8);
        float2 p1 = *reinterpret_cast<const float2*>(pr1 + nf * 8);

        // B fragments: rows nf*8..+7, chunks 0-7 via two x4 loads
        uint32_t bb1[8], bb2[8];
        int rowB = nf * 8 + rr;
        uint32_t offL = SWZ128((uint32_t)(rowB * 128 + g * 16));
        uint32_t offH = SWZ128((uint32_t)(rowB * 128 + (g + 4) * 16));
        ldsm_x4(bb1,     sbase + SMEM_B1 + offL);
        ldsm_x4(bb1 + 4, sbase + SMEM_B1 + offH);
        ldsm_x4(bb2,     sbase + SMEM_B2 + offL);
        ldsm_x4(bb2 + 4, sbase + SMEM_B2 + offH);

        float d1[4] = {0.f, 0.f, 0.f, 0.f};
        float d2[4] = {0.f, 0.f, 0.f, 0.f};
#pragma unroll
        for (int s = 0; s < 4; s++) {
            mma16816(d1, a1 + 4 * s, bb1 + 2 * s);
            mma16816(d2, a2 + 4 * s, bb2 + 2 * s);
        }

        float e0 = ex2f(d1[0] * cexp), e1 = ex2f(d1[1] * cexp);
        float e2 = ex2f(d1[2] * cexp), e3 = ex2f(d1[3] * cexp);
        rs1a += e0 + e1;  rs1b += e2 + e3;
        nm1a = fmaf(p0.x, e0, nm1a); nm1a = fmaf(p0.y, e1, nm1a);
        nm1b = fmaf(p1.x, e2, nm1b); nm1b = fmaf(p1.y, e3, nm1b);

        float f0 = ex2f(d2[0] * cexp), f1 = ex2f(d2[1] * cexp);
        float f2 = ex2f(d2[2] * cexp), f3 = ex2f(d2[3] * cexp);
        rs2a += f0 + f1;  rs2b += f2 + f3;
        nm2a = fmaf(p0.x, f0, nm2a); nm2a = fmaf(p0.y, f1, nm2a);
        nm2b = fmaf(p1.x, f2, nm2b); nm2b = fmaf(p1.y, f3, nm2b);
    }

    // ---- quad reduction (lanes differing in bits 0-1 share rows)
    float v0 = rs1a, v1 = rs1b, v2 = nm1a, v3 = nm1b;
    float v4 = rs2a, v5 = rs2b, v6 = nm2a, v7 = nm2b;
#pragma unroll
    for (int o = 1; o <= 2; o <<= 1) {
        v0 += __shfl_xor_sync(0xffffffffu, v0, o);
        v1 += __shfl_xor_sync(0xffffffffu, v1, o);
        v2 += __shfl_xor_sync(0xffffffffu, v2, o);
        v3 += __shfl_xor_sync(0xffffffffu, v3, o);
        v4 += __shfl_xor_sync(0xffffffffu, v4, o);
        v5 += __shfl_xor_sync(0xffffffffu, v5, o);
        v6 += __shfl_xor_sync(0xffffffffu, v6, o);
        v7 += __shfl_xor_sync(0xffffffffu, v7, o);
    }
    if (qc == 0) {
        atomicAdd(&g_rowsum[R0],     v0);
        atomicAdd(&g_rowsum[R0 + 8], v1);
        atomicAdd(&g_num1[R0],       v2);
        atomicAdd(&g_num1[R0 + 8],   v3);
        atomicAdd(&g_colsum[R0],     v4);
        atomicAdd(&g_colsum[R0 + 8], v5);
        atomicAdd(&g_num2[R0],       v6);
        atomicAdd(&g_num2[R0 + 8],   v7);
    }
}

// ---------------- K3: final loss reduction ----------------
__global__ void __launch_bounds__(256) final_kernel(float* __restrict__ out)
{
    __shared__ float red[8];
    int i = blockIdx.x * 256 + threadIdx.x;
    float rsum = g_rowsum[i] + 1e-8f;
    float csum = g_colsum[i] + 1e-8f;
    float term = -0.5f * (logf(g_num1[i] / rsum + 1e-8f) +
                          logf(g_num2[i] / csum + 1e-8f)) * (1.0f / NN);
#pragma unroll
    for (int o = 16; o > 0; o >>= 1) term += __shfl_xor_sync(0xffffffffu, term, o);
    int w = threadIdx.x >> 5, lane = threadIdx.x & 31;
    if (lane == 0) red[w] = term;
    __syncthreads();
    if (threadIdx.x == 0) {
        float s = 0.0f;
#pragma unroll
        for (int t = 0; t < 8; t++) s += red[t];
        atomicAdd(out, s);
    }
}

// ---------------- host launcher ----------------
extern "C" void kernel_launch(void* const* d_in, const int* in_sizes, int n_in,
                              void* d_out, int out_size)
{
    const float* x1  = (const float*)d_in[0];
    const float* x2  = (const float*)d_in[1];
    const float* W1  = (const float*)d_in[2];
    const float* b1  = (const float*)d_in[3];
    const float* W2  = (const float*)d_in[4];
    const float* b2  = (const float*)d_in[5];
    const float* pos = (const float*)d_in[6];

    void* p;
    cudaGetSymbolAddress(&p, g_rowsum); cudaMemsetAsync(p, 0, NN * sizeof(float), 0);
    cudaGetSymbolAddress(&p, g_colsum); cudaMemsetAsync(p, 0, NN * sizeof(float), 0);
    cudaGetSymbolAddress(&p, g_num1);   cudaMemsetAsync(p, 0, NN * sizeof(float), 0);
    cudaGetSymbolAddress(&p, g_num2);   cudaMemsetAsync(p, 0, NN * sizeof(float), 0);
    cudaMemsetAsync(d_out, 0, sizeof(float), 0);

    proj_kernel<<<2048, 256>>>(x1, x2, W1, b1, W2, b2);

    cudaFuncSetAttribute(sim_mma_kernel, cudaFuncAttributeMaxDynamicSharedMemorySize, SMEM_TOT);
    sim_mma_kernel<<<dim3(64, 64), 256, SMEM_TOT>>>(pos);

    final_kernel<<<32, 256>>>((float*)d_out);
}

// round 7
// speedup vs baseline: 2.4648x; 1.1876x over previous
#include <cuda_runtime.h>
#include <cuda_bf16.h>
#include <cstdint>
#include <math.h>

#define NN 8192
#define HID 64

// ---------------- device scratch (no allocs allowed) ----------------
__device__ __align__(16) __nv_bfloat16 g_z1h[NN * HID];   // normalized proj of x1 (bf16)
__device__ __align__(16) __nv_bfloat16 g_z2h[NN * HID];   // normalized proj of x2 (bf16)
__device__ float g_rowsum[NN];
__device__ float g_colsum[NN];
__device__ float g_num1[NN];
__device__ float g_num2[NN];

// ---------------- PTX helpers (baseline sm_80-class features only) ----------------
__device__ __forceinline__ uint32_t smem_u32(const void* p) {
    uint32_t a;
    asm("{ .reg .u64 t; cvta.to.shared.u64 t, %1; cvt.u32.u64 %0, t; }" : "=r"(a) : "l"(p));
    return a;
}
__device__ __forceinline__ float ex2f(float x) {
    float y; asm("ex2.approx.ftz.f32 %0, %1;" : "=f"(y) : "f"(x)); return y;
}
#define SWZ128(o) ((o) ^ (((o) >> 3) & 0x70))

__device__ __forceinline__ void ldsm_x4(uint32_t* r, uint32_t addr) {
    asm volatile("ldmatrix.sync.aligned.m8n8.x4.shared.b16 {%0,%1,%2,%3}, [%4];"
                 : "=r"(r[0]), "=r"(r[1]), "=r"(r[2]), "=r"(r[3]) : "r"(addr));
}
// D += A(16x16 bf16, row) * B(16x8 bf16, col)   [f32 accum]
__device__ __forceinline__ void mma16816(float* d, const uint32_t* a, const uint32_t* b) {
    asm volatile(
        "mma.sync.aligned.m16n8k16.row.col.f32.bf16.bf16.f32 "
        "{%0,%1,%2,%3}, {%4,%5,%6,%7}, {%8,%9}, {%0,%1,%2,%3};"
        : "+f"(d[0]), "+f"(d[1]), "+f"(d[2]), "+f"(d[3])
        : "r"(a[0]), "r"(a[1]), "r"(a[2]), "r"(a[3]), "r"(b[0]), "r"(b[1]));
}
__device__ __forceinline__ float bf2dot(uint32_t a, uint32_t b, float acc) {
    float2 fa = __bfloat1622float2(reinterpret_cast<const __nv_bfloat162&>(a));
    float2 fb = __bfloat1622float2(reinterpret_cast<const __nv_bfloat162&>(b));
    acc = fmaf(fa.x, fb.x, acc);
    return fmaf(fa.y, fb.y, acc);
}

// ---------------- K1: projection + ELU + projection + L2 norm -> bf16 ----------------
// 512 blocks; each block loads weights once and processes 4 row-groups of 8.
__global__ void __launch_bounds__(256) proj_kernel(
    const float* __restrict__ x1, const float* __restrict__ x2,
    const float* __restrict__ W1, const float* __restrict__ b1,
    const float* __restrict__ W2, const float* __restrict__ b2)
{
    __shared__ float sW1[64 * 68];
    __shared__ float sW2[64 * 68];
    __shared__ float sX[8][64];
    __shared__ float sH[8][64];

    int tid = threadIdx.x;
    {   // float4 weight loads (row stride 68 floats = 272B, 16B-aligned)
        const float4* W1f = reinterpret_cast<const float4*>(W1);
        const float4* W2f = reinterpret_cast<const float4*>(W2);
        for (int idx = tid; idx < 1024; idx += 256) {
            int r = idx >> 4, c4 = idx & 15;
            *reinterpret_cast<float4*>(sW1 + r * 68 + c4 * 4) = W1f[idx];
            *reinterpret_cast<float4*>(sW2 + r * 68 + c4 * 4) = W2f[idx];
        }
    }
    __syncthreads();

    int w = tid >> 5, lane = tid & 31;
    int c0 = lane, c1 = lane + 32;
    const float4* w1a = reinterpret_cast<const float4*>(sW1 + c0 * 68);
    const float4* w1b = reinterpret_cast<const float4*>(sW1 + c1 * 68);
    const float4* w2a = reinterpret_cast<const float4*>(sW2 + c0 * 68);
    const float4* w2b = reinterpret_cast<const float4*>(sW2 + c1 * 68);
    const float bia0 = b1[c0], bia1 = b1[c1];
    const float bib0 = b2[c0], bib1 = b2[c1];
    const float L2E = 1.4426950409f;

#pragma unroll
    for (int it = 0; it < 4; it++) {
        int slot = blockIdx.x * 8 + w + it * 4096;   // 0..16383
        const float* x; __nv_bfloat16* out; int r;
        if (slot < NN) { x = x1; out = g_z1h; r = slot; }
        else           { x = x2; out = g_z2h; r = slot - NN; }

        sX[w][lane]      = x[r * 64 + lane];
        sX[w][lane + 32] = x[r * 64 + lane + 32];
        __syncwarp();

        const float4* x4 = reinterpret_cast<const float4*>(&sX[w][0]);
        float a0 = bia0, a1 = bia1;
#pragma unroll
        for (int kq = 0; kq < 16; kq++) {
            float4 xq = x4[kq], u = w1a[kq], v = w1b[kq];
            a0 = fmaf(xq.x, u.x, a0); a0 = fmaf(xq.y, u.y, a0);
            a0 = fmaf(xq.z, u.z, a0); a0 = fmaf(xq.w, u.w, a0);
            a1 = fmaf(xq.x, v.x, a1); a1 = fmaf(xq.y, v.y, a1);
            a1 = fmaf(xq.z, v.z, a1); a1 = fmaf(xq.w, v.w, a1);
        }
        a0 = (a0 > 0.0f) ? a0 : (ex2f(a0 * L2E) - 1.0f);   // ELU alpha=1
        a1 = (a1 > 0.0f) ? a1 : (ex2f(a1 * L2E) - 1.0f);
        sH[w][c0] = a0; sH[w][c1] = a1;
        __syncwarp();

        const float4* h4 = reinterpret_cast<const float4*>(&sH[w][0]);
        float z0 = bib0, z1v = bib1;
#pragma unroll
        for (int kq = 0; kq < 16; kq++) {
            float4 hq = h4[kq], u = w2a[kq], v = w2b[kq];
            z0  = fmaf(hq.x, u.x, z0);  z0  = fmaf(hq.y, u.y, z0);
            z0  = fmaf(hq.z, u.z, z0);  z0  = fmaf(hq.w, u.w, z0);
            z1v = fmaf(hq.x, v.x, z1v); z1v = fmaf(hq.y, v.y, z1v);
            z1v = fmaf(hq.z, v.z, z1v); z1v = fmaf(hq.w, v.w, z1v);
        }
        float ss = z0 * z0 + z1v * z1v;
#pragma unroll
        for (int o = 16; o > 0; o >>= 1) ss += __shfl_xor_sync(0xffffffffu, ss, o);
        float inv = 1.0f / fmaxf(sqrtf(ss), 1e-12f);
        out[r * 64 + c0] = __float2bfloat16(z0 * inv);
        out[r * 64 + c1] = __float2bfloat16(z1v * inv);
        __syncwarp();
    }
}

// ---------------- K2: single-MMA similarity, all reductions from T1 ----------------
// Block (bi,bj): T1 = z1[bi] @ z2[bj]^T.
//   rowsum/num1 : row-aligned (quad shfl reduce + atomics)
//   colsum      : cross-qr shfl reduce -> per-warp smem slice -> block reduce
//   num2        : sparse — nonzero pos[r,c] queued, processed at block end as a
//                 64-dim bf16 dot z1[c].z2[r] from L2-resident z arrays.
#define SMEM_A   0
#define SMEM_B   16384
#define SMEM_COL 32768                // 8 warps x 128 floats = 4096 B
#define SMEM_CNT 36864                // 16 B (counter)
#define SMEM_Q   36880                // 2048 x u32 = 8192 B
#define SMEM_TOT 45072
#define QCAP 2048

__global__ void __launch_bounds__(256, 4) sim_mma_kernel(const float* __restrict__ pos)
{
    extern __shared__ char smem[];
    uint32_t sbase = smem_u32(smem);
    float* sCol = reinterpret_cast<float*>(smem + SMEM_COL);
    int*   sCnt = reinterpret_cast<int*>(smem + SMEM_CNT);
    uint32_t* sQ = reinterpret_cast<uint32_t*>(smem + SMEM_Q);

    int tid = threadIdx.x, w = tid >> 5, lane = tid & 31;
    int bi = blockIdx.y, bj = blockIdx.x;

    if (tid == 0) *sCnt = 0;

    // ---- load 2 bf16 tiles (SW128-swizzled): A=z1[bi], B=z2[bj]
    {
        const float4* z1f = reinterpret_cast<const float4*>(g_z1h);
        const float4* z2f = reinterpret_cast<const float4*>(g_z2h);
        const float4* srcA = z1f + bi * 1024;
        const float4* srcB = z2f + bj * 1024;
        for (int idx = tid; idx < 1024; idx += 256) {
            int rrow = idx >> 3, q = idx & 7;
            uint32_t sw = SWZ128((uint32_t)(rrow * 128 + q * 16));
            *reinterpret_cast<float4*>(smem + SMEM_A + sw) = srcA[idx];
            *reinterpret_cast<float4*>(smem + SMEM_B + sw) = srcB[idx];
        }
    }
    __syncthreads();

    // ---- A fragments (rows 16w..16w+15, K=64), loaded once
    int rr = lane & 7, g = lane >> 3;
    uint32_t a[16];
    {
        int rowA = 16 * w + (g & 1) * 8 + rr;
        int chA  = (g >> 1);
#pragma unroll
        for (int s = 0; s < 4; s++) {
            uint32_t off = SWZ128((uint32_t)(rowA * 128 + (2 * s + chA) * 16));
            ldsm_x4(a + 4 * s, sbase + SMEM_A + off);
        }
    }

    int qr = lane >> 2, qc = lane & 3;
    int R0 = bi * 128 + 16 * w + qr;
    int rloc0 = 16 * w + qr;                       // local row
    const float* pr0 = pos + (size_t)R0 * NN + bj * 128 + 2 * qc;
    const float* pr1 = pr0 + (size_t)8 * NN;

    float rs1a = 0.f, rs1b = 0.f, nm1a = 0.f, nm1b = 0.f;
    const float cexp = 1.8033688011f;              // log2(e)/tau

#pragma unroll
    for (int nf = 0; nf < 16; nf++) {
        float2 p0 = *reinterpret_cast<const float2*>(pr0 + nf * 8);
        float2 p1 = *reinterpret_cast<const float2*>(pr1 + nf * 8);

        uint32_t bb[8];
        int rowB = nf * 8 + rr;
        uint32_t offL = SWZ128((uint32_t)(rowB * 128 + g * 16));
        uint32_t offH = SWZ128((uint32_t)(rowB * 128 + (g + 4) * 16));
        ldsm_x4(bb,     sbase + SMEM_B + offL);
        ldsm_x4(bb + 4, sbase + SMEM_B + offH);

        float d[4] = {0.f, 0.f, 0.f, 0.f};
#pragma unroll
        for (int s = 0; s < 4; s++) mma16816(d, a + 4 * s, bb + 2 * s);

        float e0 = ex2f(d[0] * cexp), e1 = ex2f(d[1] * cexp);
        float e2 = ex2f(d[2] * cexp), e3 = ex2f(d[3] * cexp);

        rs1a += e0 + e1;  rs1b += e2 + e3;
        nm1a = fmaf(p0.x, e0, nm1a); nm1a = fmaf(p0.y, e1, nm1a);
        nm1b = fmaf(p1.x, e2, nm1b); nm1b = fmaf(p1.y, e3, nm1b);

        // colsum: reduce over qr (both row halves), lanes 0..3 store once
        float c0v = e0 + e2, c1v = e1 + e3;
#pragma unroll
        for (int o = 4; o <= 16; o <<= 1) {
            c0v += __shfl_xor_sync(0xffffffffu, c0v, o);
            c1v += __shfl_xor_sync(0xffffffffu, c1v, o);
        }
        if (lane < 4) {
            sCol[w * 128 + nf * 8 + 2 * lane]     = c0v;
            sCol[w * 128 + nf * 8 + 2 * lane + 1] = c1v;
        }

        // sparse num2 queue (rare)
        int cloc0 = nf * 8 + 2 * qc;
        if (p0.x != 0.0f) { int q_ = atomicAdd(sCnt, 1); if (q_ < QCAP) sQ[q_] = (uint32_t)((rloc0 << 8) | cloc0); }
        if (p0.y != 0.0f) { int q_ = atomicAdd(sCnt, 1); if (q_ < QCAP) sQ[q_] = (uint32_t)((rloc0 << 8) | (cloc0 + 1)); }
        if (p1.x != 0.0f) { int q_ = atomicAdd(sCnt, 1); if (q_ < QCAP) sQ[q_] = (uint32_t)(((rloc0 + 8) << 8) | cloc0); }
        if (p1.y != 0.0f) { int q_ = atomicAdd(sCnt, 1); if (q_ < QCAP) sQ[q_] = (uint32_t)(((rloc0 + 8) << 8) | (cloc0 + 1)); }
    }

    // ---- rowsum/num1: quad reduce (over qc), leaders do atomics
#pragma unroll
    for (int o = 1; o <= 2; o <<= 1) {
        rs1a += __shfl_xor_sync(0xffffffffu, rs1a, o);
        rs1b += __shfl_xor_sync(0xffffffffu, rs1b, o);
        nm1a += __shfl_xor_sync(0xffffffffu, nm1a, o);
        nm1b += __shfl_xor_sync(0xffffffffu, nm1b, o);
    }
    if (qc == 0) {
        atomicAdd(&g_rowsum[R0],     rs1a);
        atomicAdd(&g_rowsum[R0 + 8], rs1b);
        atomicAdd(&g_num1[R0],       nm1a);
        atomicAdd(&g_num1[R0 + 8],   nm1b);
    }

    __syncthreads();

    // ---- colsum: reduce 8 warp slices
    if (tid < 128) {
        float s = 0.0f;
#pragma unroll
        for (int t = 0; t < 8; t++) s += sCol[t * 128 + tid];
        atomicAdd(&g_colsum[bj * 128 + tid], s);
    }

    // ---- sparse num2: one 64-dim bf16 dot per queued nonzero
    int cnt = *sCnt; if (cnt > QCAP) cnt = QCAP;
    for (int t = tid; t < cnt; t += 256) {
        uint32_t ent = sQ[t];
        int r_ = ent >> 8, c_ = ent & 255;
        int gr = bi * 128 + r_;
        int gc = bj * 128 + c_;
        const uint4* v1 = reinterpret_cast<const uint4*>(g_z1h + (size_t)gc * 64);
        const uint4* v2 = reinterpret_cast<const uint4*>(g_z2h + (size_t)gr * 64);
        float dot = 0.0f;
#pragma unroll
        for (int q_ = 0; q_ < 8; q_++) {
            uint4 u = v1[q_], v = v2[q_];
            dot = bf2dot(u.x, v.x, dot);
            dot = bf2dot(u.y, v.y, dot);
            dot = bf2dot(u.z, v.z, dot);
            dot = bf2dot(u.w, v.w, dot);
        }
        atomicAdd(&g_num2[gr], ex2f(dot * cexp));
    }
}

// ---------------- K3: final loss reduction ----------------
__global__ void __launch_bounds__(256) final_kernel(float* __restrict__ out)
{
    __shared__ float red[8];
    int i = blockIdx.x * 256 + threadIdx.x;
    float rsum = g_rowsum[i] + 1e-8f;
    float csum = g_colsum[i] + 1e-8f;
    float term = -0.5f * (logf(g_num1[i] / rsum + 1e-8f) +
                          logf(g_num2[i] / csum + 1e-8f)) * (1.0f / NN);
#pragma unroll
    for (int o = 16; o > 0; o >>= 1) term += __shfl_xor_sync(0xffffffffu, term, o);
    int w = threadIdx.x >> 5, lane = threadIdx.x & 31;
    if (lane == 0) red[w] = term;
    __syncthreads();
    if (threadIdx.x == 0) {
        float s = 0.0f;
#pragma unroll
        for (int t = 0; t < 8; t++) s += red[t];
        atomicAdd(out, s);
    }
}

// ---------------- host launcher ----------------
extern "C" void kernel_launch(void* const* d_in, const int* in_sizes, int n_in,
                              void* d_out, int out_size)
{
    const float* x1  = (const float*)d_in[0];
    const float* x2  = (const float*)d_in[1];
    const float* W1  = (const float*)d_in[2];
    const float* b1  = (const float*)d_in[3];
    const float* W2  = (const float*)d_in[4];
    const float* b2  = (const float*)d_in[5];
    const float* pos = (const float*)d_in[6];

    void* p;
    cudaGetSymbolAddress(&p, g_rowsum); cudaMemsetAsync(p, 0, NN * sizeof(float), 0);
    cudaGetSymbolAddress(&p, g_colsum); cudaMemsetAsync(p, 0, NN * sizeof(float), 0);
    cudaGetSymbolAddress(&p, g_num1);   cudaMemsetAsync(p, 0, NN * sizeof(float), 0);
    cudaGetSymbolAddress(&p, g_num2);   cudaMemsetAsync(p, 0, NN * sizeof(float), 0);
    cudaMemsetAsync(d_out, 0, sizeof(float), 0);

    proj_kernel<<<512, 256>>>(x1, x2, W1, b1, W2, b2);

    cudaFuncSetAttribute(sim_mma_kernel, cudaFuncAttributeMaxDynamicSharedMemorySize, SMEM_TOT);
    sim_mma_kernel<<<dim3(64, 64), 256, SMEM_TOT>>>(pos);

    final_kernel<<<32, 256>>>((float*)d_out);
}

// round 8
// speedup vs baseline: 2.4931x; 1.0115x over previous
#include <cuda_runtime.h>
#include <cuda_bf16.h>
#include <cstdint>
#include <math.h>

#define NN 8192
#define HID 64

// ---------------- device scratch (no allocs allowed) ----------------
__device__ __align__(16) __nv_bfloat16 g_z1h[NN * HID];   // normalized proj of x1 (bf16)
__device__ __align__(16) __nv_bfloat16 g_z2h[NN * HID];   // normalized proj of x2 (bf16)
__device__ float g_rowsum[NN];
__device__ float g_colsum[NN];
__device__ float g_num1[NN];
__device__ float g_num2[NN];

// ---------------- PTX helpers (baseline sm_80-class features only) ----------------
__device__ __forceinline__ uint32_t smem_u32(const void* p) {
    uint32_t a;
    asm("{ .reg .u64 t; cvta.to.shared.u64 t, %1; cvt.u32.u64 %0, t; }" : "=r"(a) : "l"(p));
    return a;
}
__device__ __forceinline__ float ex2f(float x) {
    float y; asm("ex2.approx.ftz.f32 %0, %1;" : "=f"(y) : "f"(x)); return y;
}
#define SWZ128(o) ((o) ^ (((o) >> 3) & 0x70))

__device__ __forceinline__ void ldsm_x4(uint32_t* r, uint32_t addr) {
    asm volatile("ldmatrix.sync.aligned.m8n8.x4.shared.b16 {%0,%1,%2,%3}, [%4];"
                 : "=r"(r[0]), "=r"(r[1]), "=r"(r[2]), "=r"(r[3]) : "r"(addr));
}
// D += A(16x16 bf16, row) * B(16x8 bf16, col)   [f32 accum]
__device__ __forceinline__ void mma16816(float* d, const uint32_t* a, const uint32_t* b) {
    asm volatile(
        "mma.sync.aligned.m16n8k16.row.col.f32.bf16.bf16.f32 "
        "{%0,%1,%2,%3}, {%4,%5,%6,%7}, {%8,%9}, {%0,%1,%2,%3};"
        : "+f"(d[0]), "+f"(d[1]), "+f"(d[2]), "+f"(d[3])
        : "r"(a[0]), "r"(a[1]), "r"(a[2]), "r"(a[3]), "r"(b[0]), "r"(b[1]));
}
__device__ __forceinline__ float bf2dot(uint32_t a, uint32_t b, float acc) {
    float2 fa = __bfloat1622float2(reinterpret_cast<const __nv_bfloat162&>(a));
    float2 fb = __bfloat1622float2(reinterpret_cast<const __nv_bfloat162&>(b));
    acc = fmaf(fa.x, fb.x, acc);
    return fmaf(fa.y, fb.y, acc);
}

// ---------------- K1: projection + ELU + projection + L2 norm -> bf16 ----------------
// 512 blocks; each block loads weights once; each warp handles 2 rows per
// iteration (4 independent FMA chains, weight LDS amortized 2x), 2 iterations.
__global__ void __launch_bounds__(256, 3) proj_kernel(
    const float* __restrict__ x1, const float* __restrict__ x2,
    const float* __restrict__ W1, const float* __restrict__ b1,
    const float* __restrict__ W2, const float* __restrict__ b2)
{
    __shared__ float sW1[64 * 68];
    __shared__ float sW2[64 * 68];
    __shared__ float sX[8][2][64];
    __shared__ float sH[8][2][64];

    int tid = threadIdx.x;
    {   // float4 weight loads
        const float4* W1f = reinterpret_cast<const float4*>(W1);
        const float4* W2f = reinterpret_cast<const float4*>(W2);
        for (int idx = tid; idx < 1024; idx += 256) {
            int r = idx >> 4, c4 = idx & 15;
            *reinterpret_cast<float4*>(sW1 + r * 68 + c4 * 4) = W1f[idx];
            *reinterpret_cast<float4*>(sW2 + r * 68 + c4 * 4) = W2f[idx];
        }
    }
    __syncthreads();

    int w = tid >> 5, lane = tid & 31;
    int c0 = lane, c1 = lane + 32;
    const float4* w1a = reinterpret_cast<const float4*>(sW1 + c0 * 68);
    const float4* w1b = reinterpret_cast<const float4*>(sW1 + c1 * 68);
    const float4* w2a = reinterpret_cast<const float4*>(sW2 + c0 * 68);
    const float4* w2b = reinterpret_cast<const float4*>(sW2 + c1 * 68);
    const float bia0 = b1[c0], bia1 = b1[c1];
    const float bib0 = b2[c0], bib1 = b2[c1];
    const float L2E = 1.4426950409f;

#pragma unroll
    for (int it = 0; it < 2; it++) {
        int rbase = blockIdx.x * 16 + w * 2;        // rows rbase, rbase+1
        const float* x = it ? x2 : x1;
        __nv_bfloat16* out = it ? g_z2h : g_z1h;

        sX[w][0][lane]      = x[rbase * 64 + lane];
        sX[w][0][lane + 32] = x[rbase * 64 + lane + 32];
        sX[w][1][lane]      = x[(rbase + 1) * 64 + lane];
        sX[w][1][lane + 32] = x[(rbase + 1) * 64 + lane + 32];
        __syncwarp();

        const float4* xA = reinterpret_cast<const float4*>(&sX[w][0][0]);
        const float4* xB = reinterpret_cast<const float4*>(&sX[w][1][0]);
        float a0A = bia0, a1A = bia1, a0B = bia0, a1B = bia1;
#pragma unroll
        for (int kq = 0; kq < 16; kq++) {
            float4 u = w1a[kq], v = w1b[kq];
            float4 qa = xA[kq], qb = xB[kq];
            a0A = fmaf(qa.x, u.x, a0A); a0A = fmaf(qa.y, u.y, a0A);
            a0A = fmaf(qa.z, u.z, a0A); a0A = fmaf(qa.w, u.w, a0A);
            a1A = fmaf(qa.x, v.x, a1A); a1A = fmaf(qa.y, v.y, a1A);
            a1A = fmaf(qa.z, v.z, a1A); a1A = fmaf(qa.w, v.w, a1A);
            a0B = fmaf(qb.x, u.x, a0B); a0B = fmaf(qb.y, u.y, a0B);
            a0B = fmaf(qb.z, u.z, a0B); a0B = fmaf(qb.w, u.w, a0B);
            a1B = fmaf(qb.x, v.x, a1B); a1B = fmaf(qb.y, v.y, a1B);
            a1B = fmaf(qb.z, v.z, a1B); a1B = fmaf(qb.w, v.w, a1B);
        }
        a0A = (a0A > 0.0f) ? a0A : (ex2f(a0A * L2E) - 1.0f);   // ELU alpha=1
        a1A = (a1A > 0.0f) ? a1A : (ex2f(a1A * L2E) - 1.0f);
        a0B = (a0B > 0.0f) ? a0B : (ex2f(a0B * L2E) - 1.0f);
        a1B = (a1B > 0.0f) ? a1B : (ex2f(a1B * L2E) - 1.0f);
        sH[w][0][c0] = a0A; sH[w][0][c1] = a1A;
        sH[w][1][c0] = a0B; sH[w][1][c1] = a1B;
        __syncwarp();

        const float4* hA = reinterpret_cast<const float4*>(&sH[w][0][0]);
        const float4* hB = reinterpret_cast<const float4*>(&sH[w][1][0]);
        float z0A = bib0, z1A = bib1, z0B = bib0, z1B = bib1;
#pragma unroll
        for (int kq = 0; kq < 16; kq++) {
            float4 u = w2a[kq], v = w2b[kq];
            float4 qa = hA[kq], qb = hB[kq];
            z0A = fmaf(qa.x, u.x, z0A); z0A = fmaf(qa.y, u.y, z0A);
            z0A = fmaf(qa.z, u.z, z0A); z0A = fmaf(qa.w, u.w, z0A);
            z1A = fmaf(qa.x, v.x, z1A); z1A = fmaf(qa.y, v.y, z1A);
            z1A = fmaf(qa.z, v.z, z1A); z1A = fmaf(qa.w, v.w, z1A);
            z0B = fmaf(qb.x, u.x, z0B); z0B = fmaf(qb.y, u.y, z0B);
            z0B = fmaf(qb.z, u.z, z0B); z0B = fmaf(qb.w, u.w, z0B);
            z1B = fmaf(qb.x, v.x, z1B); z1B = fmaf(qb.y, v.y, z1B);
            z1B = fmaf(qb.z, v.z, z1B); z1B = fmaf(qb.w, v.w, z1B);
        }
        float ssA = z0A * z0A + z1A * z1A;
        float ssB = z0B * z0B + z1B * z1B;
#pragma unroll
        for (int o = 16; o > 0; o >>= 1) {
            ssA += __shfl_xor_sync(0xffffffffu, ssA, o);
            ssB += __shfl_xor_sync(0xffffffffu, ssB, o);
        }
        float invA = 1.0f / fmaxf(sqrtf(ssA), 1e-12f);
        float invB = 1.0f / fmaxf(sqrtf(ssB), 1e-12f);
        out[rbase * 64 + c0]       = __float2bfloat16(z0A * invA);
        out[rbase * 64 + c1]       = __float2bfloat16(z1A * invA);
        out[(rbase + 1) * 64 + c0] = __float2bfloat16(z0B * invB);
        out[(rbase + 1) * 64 + c1] = __float2bfloat16(z1B * invB);
        __syncwarp();
    }
}

// ---------------- K2: single-MMA similarity, all reductions from T1 ----------------
#define SMEM_A   0
#define SMEM_B   16384
#define SMEM_COL 32768                // 8 warps x 128 floats = 4096 B
#define SMEM_CNT 36864                // 16 B (counter)
#define SMEM_Q   36880                // 512 x u32 = 2048 B
#define SMEM_TOT 38928
#define QCAP 512

__global__ void __launch_bounds__(256, 3) sim_mma_kernel(const float* __restrict__ pos)
{
    extern __shared__ char smem[];
    uint32_t sbase = smem_u32(smem);
    float* sCol = reinterpret_cast<float*>(smem + SMEM_COL);
    int*   sCnt = reinterpret_cast<int*>(smem + SMEM_CNT);
    uint32_t* sQ = reinterpret_cast<uint32_t*>(smem + SMEM_Q);

    int tid = threadIdx.x, w = tid >> 5, lane = tid & 31;
    int bi = blockIdx.y, bj = blockIdx.x;

    if (tid == 0) *sCnt = 0;

    // ---- load 2 bf16 tiles (SW128-swizzled): A=z1[bi], B=z2[bj]
    {
        const float4* srcA = reinterpret_cast<const float4*>(g_z1h) + bi * 1024;
        const float4* srcB = reinterpret_cast<const float4*>(g_z2h) + bj * 1024;
        for (int idx = tid; idx < 1024; idx += 256) {
            int rrow = idx >> 3, q = idx & 7;
            uint32_t sw = SWZ128((uint32_t)(rrow * 128 + q * 16));
            *reinterpret_cast<float4*>(smem + SMEM_A + sw) = srcA[idx];
            *reinterpret_cast<float4*>(smem + SMEM_B + sw) = srcB[idx];
        }
    }
    __syncthreads();

    // ---- A fragments (rows 16w..16w+15, K=64), loaded once
    int rr = lane & 7, g = lane >> 3;
    uint32_t a[16];
    {
        int rowA = 16 * w + (g & 1) * 8 + rr;
        int chA  = (g >> 1);
#pragma unroll
        for (int s = 0; s < 4; s++) {
            uint32_t off = SWZ128((uint32_t)(rowA * 128 + (2 * s + chA) * 16));
            ldsm_x4(a + 4 * s, sbase + SMEM_A + off);
        }
    }

    int qr = lane >> 2, qc = lane & 3;
    int R0 = bi * 128 + 16 * w + qr;
    int rloc0 = 16 * w + qr;
    const float* pr0 = pos + (size_t)R0 * NN + bj * 128 + 2 * qc;
    const float* pr1 = pr0 + (size_t)8 * NN;

    float rs1a = 0.f, rs1b = 0.f, nm1a = 0.f, nm1b = 0.f;
    const float cexp = 1.8033688011f;              // log2(e)/tau

    // ---- software pipeline: prefetch B-fragments and pos one nf ahead
    uint32_t bb[2][8];
    {
        int rowB = rr;
        uint32_t offL = SWZ128((uint32_t)(rowB * 128 + g * 16));
        uint32_t offH = SWZ128((uint32_t)(rowB * 128 + (g + 4) * 16));
        ldsm_x4(bb[0],     sbase + SMEM_B + offL);
        ldsm_x4(bb[0] + 4, sbase + SMEM_B + offH);
    }
    float2 p0 = *reinterpret_cast<const float2*>(pr0);
    float2 p1 = *reinterpret_cast<const float2*>(pr1);

#pragma unroll
    for (int nf = 0; nf < 16; nf++) {
        int cur = nf & 1;
        // prefetch nf+1 (wraps harmlessly to 0 on the last iteration)
        int nxt = (nf + 1) & 15;
        {
            int rowB = nxt * 8 + rr;
            uint32_t offL = SWZ128((uint32_t)(rowB * 128 + g * 16));
            uint32_t offH = SWZ128((uint32_t)(rowB * 128 + (g + 4) * 16));
            ldsm_x4(bb[cur ^ 1],     sbase + SMEM_B + offL);
            ldsm_x4(bb[cur ^ 1] + 4, sbase + SMEM_B + offH);
        }
        float2 p0n = *reinterpret_cast<const float2*>(pr0 + nxt * 8);
        float2 p1n = *reinterpret_cast<const float2*>(pr1 + nxt * 8);

        float d[4] = {0.f, 0.f, 0.f, 0.f};
#pragma unroll
        for (int s = 0; s < 4; s++) mma16816(d, a + 4 * s, bb[cur] + 2 * s);

        float e0 = ex2f(d[0] * cexp), e1 = ex2f(d[1] * cexp);
        float e2 = ex2f(d[2] * cexp), e3 = ex2f(d[3] * cexp);

        rs1a += e0 + e1;  rs1b += e2 + e3;
        nm1a = fmaf(p0.x, e0, nm1a); nm1a = fmaf(p0.y, e1, nm1a);
        nm1b = fmaf(p1.x, e2, nm1b); nm1b = fmaf(p1.y, e3, nm1b);

        // colsum: reduce over qr, lanes 0..3 store once
        float c0v = e0 + e2, c1v = e1 + e3;
#pragma unroll
        for (int o = 4; o <= 16; o <<= 1) {
            c0v += __shfl_xor_sync(0xffffffffu, c0v, o);
            c1v += __shfl_xor_sync(0xffffffffu, c1v, o);
        }
        if (lane < 4) {
            sCol[w * 128 + nf * 8 + 2 * lane]     = c0v;
            sCol[w * 128 + nf * 8 + 2 * lane + 1] = c1v;
        }

        // sparse num2 queue, warp-ballot guarded (most fragments all-zero)
        bool nz = (p0.x != 0.0f) | (p0.y != 0.0f) | (p1.x != 0.0f) | (p1.y != 0.0f);
        if (__any_sync(0xffffffffu, nz)) {
            int cloc0 = nf * 8 + 2 * qc;
            if (p0.x != 0.0f) { int q_ = atomicAdd(sCnt, 1); if (q_ < QCAP) sQ[q_] = (uint32_t)((rloc0 << 8) | cloc0); }
            if (p0.y != 0.0f) { int q_ = atomicAdd(sCnt, 1); if (q_ < QCAP) sQ[q_] = (uint32_t)((rloc0 << 8) | (cloc0 + 1)); }
            if (p1.x != 0.0f) { int q_ = atomicAdd(sCnt, 1); if (q_ < QCAP) sQ[q_] = (uint32_t)(((rloc0 + 8) << 8) | cloc0); }
            if (p1.y != 0.0f) { int q_ = atomicAdd(sCnt, 1); if (q_ < QCAP) sQ[q_] = (uint32_t)(((rloc0 + 8) << 8) | (cloc0 + 1)); }
        }
        p0 = p0n; p1 = p1n;
    }

    // ---- rowsum/num1: quad reduce (over qc), leaders do atomics
#pragma unroll
    for (int o = 1; o <= 2; o <<= 1) {
        rs1a += __shfl_xor_sync(0xffffffffu, rs1a, o);
        rs1b += __shfl_xor_sync(0xffffffffu, rs1b, o);
        nm1a += __shfl_xor_sync(0xffffffffu, nm1a, o);
        nm1b += __shfl_xor_sync(0xffffffffu, nm1b, o);
    }
    if (qc == 0) {
        atomicAdd(&g_rowsum[R0],     rs1a);
        atomicAdd(&g_rowsum[R0 + 8], rs1b);
        atomicAdd(&g_num1[R0],       nm1a);
        atomicAdd(&g_num1[R0 + 8],   nm1b);
    }

    __syncthreads();

    // ---- colsum: reduce 8 warp slices
    if (tid < 128) {
        float s = 0.0f;
#pragma unroll
        for (int t = 0; t < 8; t++) s += sCol[t * 128 + tid];
        atomicAdd(&g_colsum[bj * 128 + tid], s);
    }

    // ---- sparse num2: one 64-dim bf16 dot per queued nonzero
    int cnt = *sCnt; if (cnt > QCAP) cnt = QCAP;
    for (int t = tid; t < cnt; t += 256) {
        uint32_t ent = sQ[t];
        int r_ = ent >> 8, c_ = ent & 255;
        int gr = bi * 128 + r_;
        int gc = bj * 128 + c_;
        const uint4* v1 = reinterpret_cast<const uint4*>(g_z1h + (size_t)gc * 64);
        const uint4* v2 = reinterpret_cast<const uint4*>(g_z2h + (size_t)gr * 64);
        float dot = 0.0f;
#pragma unroll
        for (int q_ = 0; q_ < 8; q_++) {
            uint4 u = v1[q_], v = v2[q_];
            dot = bf2dot(u.x, v.x, dot);
            dot = bf2dot(u.y, v.y, dot);
            dot = bf2dot(u.z, v.z, dot);
            dot = bf2dot(u.w, v.w, dot);
        }
        atomicAdd(&g_num2[gr], ex2f(dot * cexp));
    }
}

// ---------------- K3: final loss reduction ----------------
__global__ void __launch_bounds__(256) final_kernel(float* __restrict__ out)
{
    __shared__ float red[8];
    int i = blockIdx.x * 256 + threadIdx.x;
    float rsum = g_rowsum[i] + 1e-8f;
    float csum = g_colsum[i] + 1e-8f;
    float term = -0.5f * (logf(g_num1[i] / rsum + 1e-8f) +
                          logf(g_num2[i] / csum + 1e-8f)) * (1.0f / NN);
#pragma unroll
    for (int o = 16; o > 0; o >>= 1) term += __shfl_xor_sync(0xffffffffu, term, o);
    int w = threadIdx.x >> 5, lane = threadIdx.x & 31;
    if (lane == 0) red[w] = term;
    __syncthreads();
    if (threadIdx.x == 0) {
        float s = 0.0f;
#pragma unroll
        for (int t = 0; t < 8; t++) s += red[t];
        atomicAdd(out, s);
    }
}

// ---------------- host launcher ----------------
extern "C" void kernel_launch(void* const* d_in, const int* in_sizes, int n_in,
                              void* d_out, int out_size)
{
    const float* x1  = (const float*)d_in[0];
    const float* x2  = (const float*)d_in[1];
    const float* W1  = (const float*)d_in[2];
    const float* b1  = (const float*)d_in[3];
    const float* W2  = (const float*)d_in[4];
    const float* b2  = (const float*)d_in[5];
    const float* pos = (const float*)d_in[6];

    void* p;
    cudaGetSymbolAddress(&p, g_rowsum); cudaMemsetAsync(p, 0, NN * sizeof(float), 0);
    cudaGetSymbolAddress(&p, g_colsum); cudaMemsetAsync(p, 0, NN * sizeof(float), 0);
    cudaGetSymbolAddress(&p, g_num1);   cudaMemsetAsync(p, 0, NN * sizeof(float), 0);
    cudaGetSymbolAddress(&p, g_num2);   cudaMemsetAsync(p, 0, NN * sizeof(float), 0);
    cudaMemsetAsync(d_out, 0, sizeof(float), 0);

    proj_kernel<<<512, 256>>>(x1, x2, W1, b1, W2, b2);

    cudaFuncSetAttribute(sim_mma_kernel, cudaFuncAttributeMaxDynamicSharedMemorySize, SMEM_TOT);
    sim_mma_kernel<<<dim3(64, 64), 256, SMEM_TOT>>>(pos);

    final_kernel<<<32, 256>>>((float*)d_out);
}